// round 15
// baseline (speedup 1.0000x reference)
#include <cuda_runtime.h>
#include <cuda_fp16.h>

#define NB 16
#define HH 512
#define WW 512
#define HQ 256
#define WQ 256
#define RAD 7
#define NDIFF 512          // diff work units (== old diff_h blocks)
#define NV 384             // v work units (== old k_v blocks)
#define RGRP 16
#define WROWS (RGRP + 2 * RAD)   // 30

// Scratch (device globals; allocation in kernel_launch is forbidden)
__device__ __half g_yh[NB * HH * WW];
__device__ __half g_ch[2 * NB * HQ * WQ];
__device__ double g_acc[2];
__device__ unsigned g_q1, g_q2, g_done;
__device__ unsigned g_imgdone[NB];

__global__ void k_zero() {
    int t = threadIdx.x;
    if (t < 2) g_acc[t] = 0.0;
    if (t == 2) g_q1 = 0u;
    if (t == 3) g_q2 = 0u;
    if (t == 4) g_done = 0u;
    if (t >= 8 && t < 8 + NB) g_imgdone[t - 8] = 0u;
}

// ---------------------------------------------------------------------------
// diff unit u (0..511): YUV420 diff + horizontal 15-tap box, fp16 out.
// One warp = one Y row-pair = one chroma row; 8 warps per unit.
// ---------------------------------------------------------------------------
__device__ __forceinline__ void diff_unit(
    int u, const float* __restrict__ in, const float* __restrict__ tg,
    float (*sP)[WW + 16], float (*sC)[2 * WQ])
{
    const unsigned FULL = 0xFFFFFFFFu;
    int warp = threadIdx.x >> 5;
    int lane = threadIdx.x & 31;

    int gw = u * 8 + warp;
    int n  = gw >> 8;
    int hq = gw & 255;

    const long plane = (long)HH * WW;
    const long p4 = plane >> 2, w4 = WW >> 2;
    long base4 = ((long)n * 3 * plane + (long)(2 * hq) * WW) >> 2;

    const float4* i4 = (const float4*)in;
    const float4* t4 = (const float4*)tg;

    float* U = sC[warp];
    float* V = sC[warp] + WQ;
    float* P = sP[warp];

    float4 yd0[4], yd1[4];

    #pragma unroll
    for (int c = 0; c < 4; ++c) {
        long o = base4 + c * 32 + lane;
        float4 a, b, dr0, dg0, db0, dr1, dg1, db1;
        a = __ldcs(i4 + o);             b = __ldcs(t4 + o);
        dr0 = make_float4(a.x-b.x, a.y-b.y, a.z-b.z, a.w-b.w);
        a = __ldcs(i4 + o + p4);        b = __ldcs(t4 + o + p4);
        dg0 = make_float4(a.x-b.x, a.y-b.y, a.z-b.z, a.w-b.w);
        a = __ldcs(i4 + o + 2*p4);      b = __ldcs(t4 + o + 2*p4);
        db0 = make_float4(a.x-b.x, a.y-b.y, a.z-b.z, a.w-b.w);
        a = __ldcs(i4 + o + w4);        b = __ldcs(t4 + o + w4);
        dr1 = make_float4(a.x-b.x, a.y-b.y, a.z-b.z, a.w-b.w);
        a = __ldcs(i4 + o + w4 + p4);   b = __ldcs(t4 + o + w4 + p4);
        dg1 = make_float4(a.x-b.x, a.y-b.y, a.z-b.z, a.w-b.w);
        a = __ldcs(i4 + o + w4 + 2*p4); b = __ldcs(t4 + o + w4 + 2*p4);
        db1 = make_float4(a.x-b.x, a.y-b.y, a.z-b.z, a.w-b.w);

        yd0[c] = make_float4(0.299f*dr0.x + 0.587f*dg0.x + 0.114f*db0.x,
                             0.299f*dr0.y + 0.587f*dg0.y + 0.114f*db0.y,
                             0.299f*dr0.z + 0.587f*dg0.z + 0.114f*db0.z,
                             0.299f*dr0.w + 0.587f*dg0.w + 0.114f*db0.w);
        yd1[c] = make_float4(0.299f*dr1.x + 0.587f*dg1.x + 0.114f*db1.x,
                             0.299f*dr1.y + 0.587f*dg1.y + 0.114f*db1.y,
                             0.299f*dr1.z + 0.587f*dg1.z + 0.114f*db1.z,
                             0.299f*dr1.w + 0.587f*dg1.w + 0.114f*db1.w);

        float drA = dr0.x + dr0.y + dr1.x + dr1.y;
        float dgA = dg0.x + dg0.y + dg1.x + dg1.y;
        float dbA = db0.x + db0.y + db1.x + db1.y;
        float drB = dr0.z + dr0.w + dr1.z + dr1.w;
        float dgB = dg0.z + dg0.w + dg1.z + dg1.w;
        float dbB = db0.z + db0.w + db1.z + db1.w;

        *(float2*)(U + c*64 + 2*lane) =
            make_float2(0.25f * (-0.169f*drA - 0.331f*dgA + 0.5f*dbA),
                        0.25f * (-0.169f*drB - 0.331f*dgB + 0.5f*dbB));
        *(float2*)(V + c*64 + 2*lane) =
            make_float2(0.25f * ( 0.5f*drA - 0.46f*dgA - 0.04f*dbA),
                        0.25f * ( 0.5f*drB - 0.46f*dgB - 0.04f*dbB));
    }
    __syncwarp();

    #pragma unroll
    for (int r = 0; r < 2; ++r) {
        float4* Y = r ? yd1 : yd0;
        if (lane < 8) P[lane] = 0.f;
        float carry = 0.f;
        #pragma unroll
        for (int c = 0; c < 4; ++c) {
            float4 v = Y[c];
            float p1 = v.x + v.y, p2 = p1 + v.z, p3 = p2 + v.w;
            float tt = p3;
            #pragma unroll
            for (int off = 1; off < 32; off <<= 1) {
                float o = __shfl_up_sync(FULL, tt, off);
                if (lane >= off) tt += o;
            }
            float bb = tt - p3 + carry;
            ((float4*)(P + 8))[c * 32 + lane] =
                make_float4(bb + v.x, bb + p1, bb + p2, bb + p3);
            carry += __shfl_sync(FULL, tt, 31);
        }
        __syncwarp();
        if (lane < 7) P[8 + WW + lane] = carry;
        __syncwarp();
        __half* dst = g_yh + (long)n * plane + (long)(2*hq + r) * WW;
        #pragma unroll
        for (int c = 0; c < 4; ++c) {
            int x = c * 128 + 4 * lane;
            float4 b = ((const float4*)P)[x >> 2];
            __half2 h01 = __floats2half2_rn(P[x + 15] - b.x, P[x + 16] - b.y);
            __half2 h23 = __floats2half2_rn(P[x + 17] - b.z, P[x + 18] - b.w);
            uint2 st;
            st.x = *(unsigned*)&h01;
            st.y = *(unsigned*)&h23;
            *(uint2*)(dst + x) = st;
        }
        __syncwarp();
    }

    #pragma unroll
    for (int r = 0; r < 2; ++r) {
        const float* R = r ? V : U;
        if (lane < 8) P[lane] = 0.f;
        float carry = 0.f;
        #pragma unroll
        for (int c = 0; c < 2; ++c) {
            float4 v = ((const float4*)R)[c * 32 + lane];
            float p1 = v.x + v.y, p2 = p1 + v.z, p3 = p2 + v.w;
            float tt = p3;
            #pragma unroll
            for (int off = 1; off < 32; off <<= 1) {
                float o = __shfl_up_sync(FULL, tt, off);
                if (lane >= off) tt += o;
            }
            float bb = tt - p3 + carry;
            ((float4*)(P + 8))[c * 32 + lane] =
                make_float4(bb + v.x, bb + p1, bb + p2, bb + p3);
            carry += __shfl_sync(FULL, tt, 31);
        }
        __syncwarp();
        if (lane < 7) P[8 + WQ + lane] = carry;
        __syncwarp();
        __half* dst = g_ch + ((long)(r * NB + n) * HQ + hq) * WQ;
        #pragma unroll
        for (int c = 0; c < 2; ++c) {
            int x = c * 128 + 4 * lane;
            float4 b = ((const float4*)P)[x >> 2];
            __half2 h01 = __floats2half2_rn(P[x + 15] - b.x, P[x + 16] - b.y);
            __half2 h23 = __floats2half2_rn(P[x + 17] - b.z, P[x + 18] - b.w);
            uint2 st;
            st.x = *(unsigned*)&h01;
            st.y = *(unsigned*)&h23;
            *(uint2*)(dst + x) = st;
        }
        __syncwarp();
    }
}

// ---------------------------------------------------------------------------
// v unit v (0..383): vertical 15-tap box, MLP-batched (R12/R14 best geometry),
// fused square + reduce + finalize.
// ---------------------------------------------------------------------------
__device__ __forceinline__ void v_unit(int v, float* __restrict__ out, double* red)
{
    const unsigned FULL = 0xFFFFFFFFu;
    int t = v * 256 + threadIdx.x;
    bool isY = t < 65536;

    const __half* src; int H, y0; long stride;
    if (isY) {
        int colg = t & 127, rowg = (t >> 7) & 31, n = t >> 12;
        H = HH; stride = WW; y0 = rowg * RGRP;
        src = g_yh + (long)n * HH * WW + 4 * colg;
    } else {
        int t2 = t - 65536;
        int colg = t2 & 63, rowg = (t2 >> 6) & 15, pl = t2 >> 10;
        H = HQ; stride = WQ; y0 = rowg * RGRP;
        src = g_ch + (long)pl * HQ * WQ + 4 * colg;
    }

    uint2 r[WROWS];
    #pragma unroll
    for (int j = 0; j < WROWS; ++j) {
        int yy = y0 + j - RAD;
        if (yy >= 0 && yy < H)
            r[j] = *(const uint2*)(src + (long)yy * stride);
        else
            r[j] = make_uint2(0u, 0u);
    }

    float4 sum = make_float4(0.f, 0.f, 0.f, 0.f);
    #pragma unroll
    for (int j = 0; j < 15; ++j) {
        float2 lo = __half22float2(*(__half2*)&r[j].x);
        float2 hi = __half22float2(*(__half2*)&r[j].y);
        sum.x += lo.x; sum.y += lo.y; sum.z += hi.x; sum.w += hi.y;
    }
    float racc = 0.f;
    #pragma unroll
    for (int i = 0; i < RGRP; ++i) {
        racc += sum.x*sum.x + sum.y*sum.y + sum.z*sum.z + sum.w*sum.w;
        if (i < RGRP - 1) {
            float2 alo = __half22float2(*(__half2*)&r[i + 15].x);
            float2 ahi = __half22float2(*(__half2*)&r[i + 15].y);
            float2 rlo = __half22float2(*(__half2*)&r[i].x);
            float2 rhi = __half22float2(*(__half2*)&r[i].y);
            sum.x += alo.x - rlo.x; sum.y += alo.y - rlo.y;
            sum.z += ahi.x - rhi.x; sum.w += ahi.y - rhi.y;
        }
    }
    double dacc = (double)racc;

    #pragma unroll
    for (int off = 16; off > 0; off >>= 1)
        dacc += __shfl_down_sync(FULL, dacc, off);
    int warp = threadIdx.x >> 5, lane = threadIdx.x & 31;
    if (lane == 0) red[warp] = dacc;
    __syncthreads();
    if (threadIdx.x == 0) {
        double s = 0.0;
        #pragma unroll
        for (int w = 0; w < 8; ++w) s += red[w];
        atomicAdd(&g_acc[isY ? 0 : 1], s);
        __threadfence();
        unsigned prev = atomicAdd(&g_done, 1u);
        if (prev == NV - 1) {
            volatile double* acc = g_acc;
            double y = acc[0] / (double)((long)NB * HH * WW);
            double c = acc[1] / (double)((long)NB * HQ * WQ);
            out[0] = (float)(y + c);
        }
    }
    __syncthreads();
}

// ---------------------------------------------------------------------------
// Fused persistent kernel: queue-claimed diff units, then queue-claimed v
// units with per-image readiness spin. Deadlock-free: phase-2 spins wait only
// on diff work already claimed by running blocks.
// ---------------------------------------------------------------------------
__global__ void __launch_bounds__(256, 3)
k_fused(const float* __restrict__ in, const float* __restrict__ tg,
        float* __restrict__ out)
{
    __shared__ float sP[8][WW + 16];
    __shared__ float sC[8][2 * WQ];
    __shared__ double red[8];
    __shared__ unsigned s_claim;

    // ---- phase 1: diff units ----
    for (;;) {
        if (threadIdx.x == 0) s_claim = atomicAdd(&g_q1, 1u);
        __syncthreads();
        unsigned u = s_claim;
        if (u >= NDIFF) break;
        diff_unit((int)u, in, tg, sP, sC);
        __syncthreads();
        if (threadIdx.x == 0) {
            __threadfence();
            atomicAdd(&g_imgdone[u >> 5], 1u);
        }
        __syncthreads();
    }

    // ---- phase 2: v units, gated on per-image completion ----
    for (;;) {
        if (threadIdx.x == 0) s_claim = atomicAdd(&g_q2, 1u);
        __syncthreads();
        unsigned v = s_claim;
        if (v >= NV) break;
        int img = (v < 256u) ? (int)(v >> 4) : (int)(((v - 256u) >> 2) & 15u);
        if (threadIdx.x == 0) {
            while (atomicAdd(&g_imgdone[img], 0u) < 32u) __nanosleep(128);
        }
        __syncthreads();
        __threadfence();
        v_unit((int)v, out, red);
        __syncthreads();
    }
}

extern "C" void kernel_launch(void* const* d_in, const int* in_sizes, int n_in,
                              void* d_out, int out_size) {
    const float* in = (const float*)d_in[0];
    const float* tg = (const float*)d_in[1];
    float* out = (float*)d_out;
    (void)in_sizes; (void)n_in; (void)out_size;

    k_zero<<<1, 32>>>();
    k_fused<<<456, 256>>>(in, tg, out);
}

// round 17
// speedup vs baseline: 1.1231x; 1.1231x over previous
#include <cuda_runtime.h>
#include <cuda_fp16.h>

#define NB 16
#define HH 512
#define WW 512
#define HQ 256
#define WQ 256
#define RAD 7

// Scratch (device globals; allocation in kernel_launch is forbidden)
__device__ __half g_yh[NB * HH * WW];        // horizontally filtered Y diff (fp16)
__device__ __half g_ch[2 * NB * HQ * WQ];    // horizontally filtered chroma (fp16)
__device__ double g_acc[2];                  // [0]=Y sumsq, [1]=U+V sumsq
__device__ unsigned int g_done;              // completion counter (self-resetting)

// L2 eviction-priority via createpolicy + cache_hint (arbitrary width form).
// evict_last keeps the 24.6MB intermediate resident while the 100MB input
// stream (evict-first via __ldcs) flows through L2.
__device__ __forceinline__ unsigned long long mk_evl_policy() {
    unsigned long long p;
    asm volatile("createpolicy.fractional.L2::evict_last.b64 %0, 1.0;" : "=l"(p));
    return p;
}
__device__ __forceinline__ void st_evl(__half* p, unsigned x, unsigned y,
                                       unsigned long long pol) {
    asm volatile("st.global.L2::cache_hint.v2.u32 [%0], {%1, %2}, %3;"
                 :: "l"(p), "r"(x), "r"(y), "l"(pol) : "memory");
}
__device__ __forceinline__ uint2 ld_evl(const __half* p, unsigned long long pol) {
    uint2 v;
    asm volatile("ld.global.L2::cache_hint.v2.u32 {%0, %1}, [%2], %3;"
                 : "=r"(v.x), "=r"(v.y) : "l"(p), "l"(pol));
    return v;
}

// ---------------------------------------------------------------------------
// k_diff_h: YUV420 diff channels + horizontal 15-tap box filter, fused.
// One warp = one Y row-pair = one chroma row. grid 512, block 256 (8 warps).
// Inputs: __ldcs (single-use stream). Intermediate stores: L2 evict_last.
// ---------------------------------------------------------------------------
__global__ void __launch_bounds__(256)
k_diff_h(const float* __restrict__ in, const float* __restrict__ tg) {
    __shared__ float sP[8][WW + 16];    // per-warp prefix buffer
    __shared__ float sC[8][2 * WQ];     // per-warp raw chroma rows (U|V)

    const unsigned FULL = 0xFFFFFFFFu;
    int warp = threadIdx.x >> 5;
    int lane = threadIdx.x & 31;
    unsigned long long pol = mk_evl_policy();

    if (blockIdx.x == 0 && threadIdx.x < 2) g_acc[threadIdx.x] = 0.0;

    int gw = blockIdx.x * 8 + warp;     // 0..4095 row-pairs
    int n  = gw >> 8;                   // image
    int hq = gw & 255;                  // chroma row / y row-pair

    const long plane = (long)HH * WW;
    const long p4 = plane >> 2, w4 = WW >> 2;
    long base4 = ((long)n * 3 * plane + (long)(2 * hq) * WW) >> 2;

    const float4* i4 = (const float4*)in;
    const float4* t4 = (const float4*)tg;

    float* U = sC[warp];
    float* V = sC[warp] + WQ;
    float* P = sP[warp];

    float4 yd0[4], yd1[4];

    #pragma unroll
    for (int c = 0; c < 4; ++c) {
        long o = base4 + c * 32 + lane;
        float4 a, b, dr0, dg0, db0, dr1, dg1, db1;
        a = __ldcs(i4 + o);             b = __ldcs(t4 + o);
        dr0 = make_float4(a.x-b.x, a.y-b.y, a.z-b.z, a.w-b.w);
        a = __ldcs(i4 + o + p4);        b = __ldcs(t4 + o + p4);
        dg0 = make_float4(a.x-b.x, a.y-b.y, a.z-b.z, a.w-b.w);
        a = __ldcs(i4 + o + 2*p4);      b = __ldcs(t4 + o + 2*p4);
        db0 = make_float4(a.x-b.x, a.y-b.y, a.z-b.z, a.w-b.w);
        a = __ldcs(i4 + o + w4);        b = __ldcs(t4 + o + w4);
        dr1 = make_float4(a.x-b.x, a.y-b.y, a.z-b.z, a.w-b.w);
        a = __ldcs(i4 + o + w4 + p4);   b = __ldcs(t4 + o + w4 + p4);
        dg1 = make_float4(a.x-b.x, a.y-b.y, a.z-b.z, a.w-b.w);
        a = __ldcs(i4 + o + w4 + 2*p4); b = __ldcs(t4 + o + w4 + 2*p4);
        db1 = make_float4(a.x-b.x, a.y-b.y, a.z-b.z, a.w-b.w);

        yd0[c] = make_float4(0.299f*dr0.x + 0.587f*dg0.x + 0.114f*db0.x,
                             0.299f*dr0.y + 0.587f*dg0.y + 0.114f*db0.y,
                             0.299f*dr0.z + 0.587f*dg0.z + 0.114f*db0.z,
                             0.299f*dr0.w + 0.587f*dg0.w + 0.114f*db0.w);
        yd1[c] = make_float4(0.299f*dr1.x + 0.587f*dg1.x + 0.114f*db1.x,
                             0.299f*dr1.y + 0.587f*dg1.y + 0.114f*db1.y,
                             0.299f*dr1.z + 0.587f*dg1.z + 0.114f*db1.z,
                             0.299f*dr1.w + 0.587f*dg1.w + 0.114f*db1.w);

        float drA = dr0.x + dr0.y + dr1.x + dr1.y;
        float dgA = dg0.x + dg0.y + dg1.x + dg1.y;
        float dbA = db0.x + db0.y + db1.x + db1.y;
        float drB = dr0.z + dr0.w + dr1.z + dr1.w;
        float dgB = dg0.z + dg0.w + dg1.z + dg1.w;
        float dbB = db0.z + db0.w + db1.z + db1.w;

        *(float2*)(U + c*64 + 2*lane) =
            make_float2(0.25f * (-0.169f*drA - 0.331f*dgA + 0.5f*dbA),
                        0.25f * (-0.169f*drB - 0.331f*dgB + 0.5f*dbB));
        *(float2*)(V + c*64 + 2*lane) =
            make_float2(0.25f * ( 0.5f*drA - 0.46f*dgA - 0.04f*dbA),
                        0.25f * ( 0.5f*drB - 0.46f*dgB - 0.04f*dbB));
    }
    __syncwarp();

    // ---- horizontal box filter of one row via prefix sum, emit fp16 ----
    // Y rows from registers
    #pragma unroll
    for (int r = 0; r < 2; ++r) {
        float4* Y = r ? yd1 : yd0;
        if (lane < 8) P[lane] = 0.f;
        float carry = 0.f;
        #pragma unroll
        for (int c = 0; c < 4; ++c) {
            float4 v = Y[c];
            float p1 = v.x + v.y, p2 = p1 + v.z, p3 = p2 + v.w;
            float tt = p3;
            #pragma unroll
            for (int off = 1; off < 32; off <<= 1) {
                float o = __shfl_up_sync(FULL, tt, off);
                if (lane >= off) tt += o;
            }
            float bb = tt - p3 + carry;
            ((float4*)(P + 8))[c * 32 + lane] =
                make_float4(bb + v.x, bb + p1, bb + p2, bb + p3);
            carry += __shfl_sync(FULL, tt, 31);
        }
        __syncwarp();
        if (lane < 7) P[8 + WW + lane] = carry;
        __syncwarp();
        __half* dst = g_yh + (long)n * plane + (long)(2*hq + r) * WW;
        #pragma unroll
        for (int c = 0; c < 4; ++c) {
            int x = c * 128 + 4 * lane;
            float4 b = ((const float4*)P)[x >> 2];
            __half2 h01 = __floats2half2_rn(P[x + 15] - b.x, P[x + 16] - b.y);
            __half2 h23 = __floats2half2_rn(P[x + 17] - b.z, P[x + 18] - b.w);
            st_evl(dst + x, *(unsigned*)&h01, *(unsigned*)&h23, pol);
        }
        __syncwarp();
    }

    // Chroma rows from smem staging
    #pragma unroll
    for (int r = 0; r < 2; ++r) {
        const float* R = r ? V : U;
        if (lane < 8) P[lane] = 0.f;
        float carry = 0.f;
        #pragma unroll
        for (int c = 0; c < 2; ++c) {
            float4 v = ((const float4*)R)[c * 32 + lane];
            float p1 = v.x + v.y, p2 = p1 + v.z, p3 = p2 + v.w;
            float tt = p3;
            #pragma unroll
            for (int off = 1; off < 32; off <<= 1) {
                float o = __shfl_up_sync(FULL, tt, off);
                if (lane >= off) tt += o;
            }
            float bb = tt - p3 + carry;
            ((float4*)(P + 8))[c * 32 + lane] =
                make_float4(bb + v.x, bb + p1, bb + p2, bb + p3);
            carry += __shfl_sync(FULL, tt, 31);
        }
        __syncwarp();
        if (lane < 7) P[8 + WQ + lane] = carry;
        __syncwarp();
        __half* dst = g_ch + ((long)(r * NB + n) * HQ + hq) * WQ;
        #pragma unroll
        for (int c = 0; c < 2; ++c) {
            int x = c * 128 + 4 * lane;
            float4 b = ((const float4*)P)[x >> 2];
            __half2 h01 = __floats2half2_rn(P[x + 15] - b.x, P[x + 16] - b.y);
            __half2 h23 = __floats2half2_rn(P[x + 17] - b.z, P[x + 18] - b.w);
            st_evl(dst + x, *(unsigned*)&h01, *(unsigned*)&h23, pol);
        }
        __syncwarp();
    }
}

// ---------------------------------------------------------------------------
// k_v: vertical 15-tap box (zero-pad SAME), MLP-maximized (R12 best geometry):
// 30 up-front uint2 loads (L2 evict_last), RGRP=16, 4 fp16 cols/thread,
// 384 blocks. Blocks 0..255: Y. Blocks 256..383: chroma. Fused reduce+final.
// ---------------------------------------------------------------------------
#define NBLK_V 384
#define RGRP 16
#define WROWS (RGRP + 2 * RAD)   // 30

__global__ void __launch_bounds__(256)
k_v(float* __restrict__ out) {
    __shared__ double red[8];
    const unsigned FULL = 0xFFFFFFFFu;
    unsigned long long pol = mk_evl_policy();

    int t = blockIdx.x * 256 + threadIdx.x;
    bool isY = t < 65536;

    const __half* src; int H, y0; long stride;
    if (isY) {
        int colg = t & 127, rowg = (t >> 7) & 31, n = t >> 12;
        H = HH; stride = WW; y0 = rowg * RGRP;
        src = g_yh + (long)n * HH * WW + 4 * colg;
    } else {
        int t2 = t - 65536;
        int colg = t2 & 63, rowg = (t2 >> 6) & 15, pl = t2 >> 10;  // 0..31
        H = HQ; stride = WQ; y0 = rowg * RGRP;
        src = g_ch + (long)pl * HQ * WQ + 4 * colg;
    }

    // ---- batch-issue all 30 independent loads (max MLP) ----
    uint2 r[WROWS];
    #pragma unroll
    for (int j = 0; j < WROWS; ++j) {
        int yy = y0 + j - RAD;
        if (yy >= 0 && yy < H)
            r[j] = ld_evl(src + (long)yy * stride, pol);
        else
            r[j] = make_uint2(0u, 0u);
    }

    // ---- sliding window entirely in registers ----
    float4 sum = make_float4(0.f, 0.f, 0.f, 0.f);
    #pragma unroll
    for (int j = 0; j < 15; ++j) {
        float2 lo = __half22float2(*(__half2*)&r[j].x);
        float2 hi = __half22float2(*(__half2*)&r[j].y);
        sum.x += lo.x; sum.y += lo.y; sum.z += hi.x; sum.w += hi.y;
    }
    float racc = 0.f;
    #pragma unroll
    for (int i = 0; i < RGRP; ++i) {
        racc += sum.x*sum.x + sum.y*sum.y + sum.z*sum.z + sum.w*sum.w;
        if (i < RGRP - 1) {
            float2 alo = __half22float2(*(__half2*)&r[i + 15].x);
            float2 ahi = __half22float2(*(__half2*)&r[i + 15].y);
            float2 rlo = __half22float2(*(__half2*)&r[i].x);
            float2 rhi = __half22float2(*(__half2*)&r[i].y);
            sum.x += alo.x - rlo.x; sum.y += alo.y - rlo.y;
            sum.z += ahi.x - rhi.x; sum.w += ahi.y - rhi.y;
        }
    }
    double dacc = (double)racc;

    #pragma unroll
    for (int off = 16; off > 0; off >>= 1)
        dacc += __shfl_down_sync(FULL, dacc, off);
    int warp = threadIdx.x >> 5, lane = threadIdx.x & 31;
    if (lane == 0) red[warp] = dacc;
    __syncthreads();
    if (threadIdx.x == 0) {
        double s = 0.0;
        #pragma unroll
        for (int w = 0; w < 8; ++w) s += red[w];
        atomicAdd(&g_acc[isY ? 0 : 1], s);
        __threadfence();
        unsigned int prev = atomicAdd(&g_done, 1u);
        if (prev == NBLK_V - 1) {
            volatile double* acc = g_acc;
            double y = acc[0] / (double)((long)NB * HH * WW);
            double c = acc[1] / (double)((long)NB * HQ * WQ);
            out[0] = (float)(y + c);
            g_done = 0u;
        }
    }
}

extern "C" void kernel_launch(void* const* d_in, const int* in_sizes, int n_in,
                              void* d_out, int out_size) {
    const float* in = (const float*)d_in[0];
    const float* tg = (const float*)d_in[1];
    float* out = (float*)d_out;
    (void)in_sizes; (void)n_in; (void)out_size;

    k_diff_h<<<512, 256>>>(in, tg);
    k_v<<<NBLK_V, 256>>>(out);
}